// round 2
// baseline (speedup 1.0000x reference)
#include <cuda_runtime.h>
#include <math.h>
#include <stdint.h>

#define CB 2
#define CS 2048
#define CH 1024
#define CNH 16
#define CHD 64
#define CE 8
#define CD 1024
#define CT (CB*CS)

#define MB (1024ull*1024ull)

// ---------------- scratch layout ----------------
static constexpr size_t OFF_WQ_ATTN = 0;               // 4 MB  int8: q,k,v,o (1MB each)
static constexpr size_t OFF_WQ_GATE = 4*MB;            // 8 MB
static constexpr size_t OFF_WQ_UP   = 12*MB;           // 8 MB
static constexpr size_t OFF_WQ_DOWN = 20*MB;           // 8 MB
static constexpr size_t OFF_WSCALE  = 28*MB;           // 28 floats (dequant mult per slice)
static constexpr size_t OFF_PART    = 28*MB + 4096;    // 28*256 floats partial sums
static constexpr size_t OFF_XQ1     = 29*MB;           // 4 MB int8
static constexpr size_t OFF_A1S     = 33*MB;           // T floats
static constexpr size_t OFF_QKV     = 34*MB;           // 48 MB fp32: q,k,v [B,NH,S,HD]
static constexpr size_t OFF_HB      = 82*MB;           // 16 MB fp32 attention out [T,H]
static constexpr size_t OFF_HQA     = 98*MB;           // 4 MB int8
static constexpr size_t OFF_HSA     = 102*MB;          // T floats
static constexpr size_t OFF_X2      = 103*MB;          // 16 MB fp32 (post-attn residual)
static constexpr size_t OFF_XQ2     = 119*MB;          // 4 MB int8
static constexpr size_t OFF_A2S     = 123*MB;          // T floats
static constexpr size_t OFF_IDX     = 123*MB + 64*1024;
static constexpr size_t OFF_CNT     = 123*MB + 128*1024;   // counts[8]
static constexpr size_t OFF_SEG     = 123*MB + 129*1024;   // offsets[9]
static constexpr size_t OFF_CUR     = 123*MB + 130*1024;   // cursor[8]
static constexpr size_t OFF_PERM    = 124*MB;          // T ints
static constexpr size_t OFF_GB      = 125*MB;          // 16 MB fp32
static constexpr size_t OFF_UB      = 141*MB;          // 16 MB fp32
static constexpr size_t OFF_HQM     = 157*MB;          // 4 MB int8
static constexpr size_t OFF_HSM     = 161*MB;          // T floats
static constexpr size_t SCRATCH_BYTES = 162*MB;

__device__ __align__(256) unsigned char g_scratch[SCRATCH_BYTES];

// ---------------- helpers ----------------
__device__ __forceinline__ float blk_reduce_sum(float v, float* red) {
    int tid = threadIdx.x;
    red[tid] = v; __syncthreads();
    #pragma unroll
    for (int s = 128; s > 0; s >>= 1) {
        if (tid < s) red[tid] += red[tid + s];
        __syncthreads();
    }
    float r = red[0]; __syncthreads();
    return r;
}

__device__ __forceinline__ float blk_reduce_max(float v, float* red) {
    int tid = threadIdx.x;
    red[tid] = v; __syncthreads();
    #pragma unroll
    for (int s = 128; s > 0; s >>= 1) {
        if (tid < s) red[tid] = fmaxf(red[tid], red[tid + s]);
        __syncthreads();
    }
    float r = red[0]; __syncthreads();
    return r;
}

// ---------------- weight quantization ----------------
// partial abs-sums: grid (nb, nslice), each slice is `len` contiguous floats
__global__ void absmean_partial(const float* __restrict__ w, float* __restrict__ part, int len) {
    __shared__ float red[256];
    const float* p = w + (size_t)blockIdx.y * len;
    float s = 0.f;
    for (int i = blockIdx.x * 256 + threadIdx.x; i < len; i += gridDim.x * 256)
        s += fabsf(p[i]);
    s = blk_reduce_sum(s, red);
    if (threadIdx.x == 0) part[(size_t)blockIdx.y * gridDim.x + blockIdx.x] = s;
}

// 28 slices, each len 1M, 256 partials each
__global__ void finalize_wscale(const float* __restrict__ part, float* __restrict__ wsc) {
    int i = threadIdx.x;
    if (i >= 28) return;
    float s = 0.f;
    for (int j = 0; j < 256; j++) s += part[i * 256 + j];
    wsc[i] = fmaxf(s * (1.0f / (1024.f * 1024.f)), 1e-5f);   // dequant multiplier = clip(mean|w|,1e-5)
}

__global__ void quantize_w(const float* __restrict__ w, int8_t* __restrict__ wq,
                           const float* __restrict__ wsc, int widx0, int len) {
    int slice = blockIdx.y;
    float s = 1.0f / wsc[widx0 + slice];
    const float* p = w + (size_t)slice * len;
    int8_t* q = wq + (size_t)slice * len;
    for (int i = blockIdx.x * 256 + threadIdx.x; i < len; i += gridDim.x * 256) {
        float v = rintf(p[i] * s);
        v = fminf(fmaxf(v, -1.f), 1.f);
        q[i] = (int8_t)(int)v;
    }
}

// ---------------- activation rmsnorm + quant ----------------
__global__ void rmsnorm_quant(const float* __restrict__ x, const float* __restrict__ lnw,
                              int8_t* __restrict__ xq, float* __restrict__ ainv) {
    __shared__ float red[256];
    __shared__ float xs[CH];
    int t = blockIdx.x, tid = threadIdx.x;
    const float* xr = x + (size_t)t * CH;
    float v[4]; float ss = 0.f;
    #pragma unroll
    for (int i = 0; i < 4; i++) { v[i] = xr[tid + i * 256]; ss += v[i] * v[i]; }
    ss = blk_reduce_sum(ss, red);
    float r = rsqrtf(ss * (1.0f / CH) + 1e-5f);
    float amax = 0.f;
    #pragma unroll
    for (int i = 0; i < 4; i++) {
        float xn = v[i] * r * lnw[tid + i * 256];
        xs[tid + i * 256] = xn;
        amax = fmaxf(amax, fabsf(xn));
    }
    amax = blk_reduce_max(amax, red);
    float m = fmaxf(amax, 1e-5f);
    float s = 127.f / m;
    #pragma unroll
    for (int i = 0; i < 4; i++) {
        float qv = fminf(fmaxf(rintf(xs[tid + i * 256] * s), -128.f), 127.f);
        xq[(size_t)t * CH + tid + i * 256] = (int8_t)(int)qv;
    }
    if (tid == 0) ainv[t] = m * (1.0f / 127.f);
}

// plain act_quant over rows of length 1024
__global__ void act_quant_rows(const float* __restrict__ x, int8_t* __restrict__ xq,
                               float* __restrict__ ainv) {
    __shared__ float red[256];
    int t = blockIdx.x, tid = threadIdx.x;
    const float* xr = x + (size_t)t * CH;
    float v[4]; float amax = 0.f;
    #pragma unroll
    for (int i = 0; i < 4; i++) { v[i] = xr[tid + i * 256]; amax = fmaxf(amax, fabsf(v[i])); }
    amax = blk_reduce_max(amax, red);
    float m = fmaxf(amax, 1e-5f);
    float s = 127.f / m;
    #pragma unroll
    for (int i = 0; i < 4; i++) {
        float qv = fminf(fmaxf(rintf(v[i] * s), -128.f), 127.f);
        xq[(size_t)t * CH + tid + i * 256] = (int8_t)(int)qv;
    }
    if (tid == 0) ainv[t] = m * (1.0f / 127.f);
}

// rmsnorm2 + quant + router logits + argmax + expert count
__global__ void rmsnorm2_router(const float* __restrict__ x, const float* __restrict__ lnw,
                                const float* __restrict__ rw, int8_t* __restrict__ xq,
                                float* __restrict__ ainv, int* __restrict__ idx,
                                int* __restrict__ counts) {
    __shared__ float red[256];
    __shared__ float xs[CH];
    __shared__ float logits[CE];
    int t = blockIdx.x, tid = threadIdx.x;
    const float* xr = x + (size_t)t * CH;
    float v[4]; float ss = 0.f;
    #pragma unroll
    for (int i = 0; i < 4; i++) { v[i] = xr[tid + i * 256]; ss += v[i] * v[i]; }
    ss = blk_reduce_sum(ss, red);
    float r = rsqrtf(ss * (1.0f / CH) + 1e-5f);
    float amax = 0.f;
    #pragma unroll
    for (int i = 0; i < 4; i++) {
        float xn = v[i] * r * lnw[tid + i * 256];
        xs[tid + i * 256] = xn;
        amax = fmaxf(amax, fabsf(xn));
    }
    amax = blk_reduce_max(amax, red);
    float m = fmaxf(amax, 1e-5f);
    float s = 127.f / m;
    #pragma unroll
    for (int i = 0; i < 4; i++) {
        float qv = fminf(fmaxf(rintf(xs[tid + i * 256] * s), -128.f), 127.f);
        xq[(size_t)t * CH + tid + i * 256] = (int8_t)(int)qv;
    }
    if (tid == 0) ainv[t] = m * (1.0f / 127.f);
    __syncthreads();   // xs fully written (blk_reduce_max already synced, but be safe)

    // router: warp w computes logit for expert w
    int w = tid >> 5, lane = tid & 31;
    float acc = 0.f;
    for (int h = lane; h < CH; h += 32) acc += xs[h] * rw[w * CH + h];
    #pragma unroll
    for (int o = 16; o > 0; o >>= 1) acc += __shfl_down_sync(0xffffffffu, acc, o);
    if (lane == 0) logits[w] = acc;
    __syncthreads();
    if (tid == 0) {
        float best = logits[0]; int bi = 0;
        #pragma unroll
        for (int e = 1; e < CE; e++) if (logits[e] > best) { best = logits[e]; bi = e; }
        idx[t] = bi;
        atomicAdd(&counts[bi], 1);
    }
}

__global__ void zero_ints(int* __restrict__ counts, int* __restrict__ cursor) {
    if (threadIdx.x < CE) { counts[threadIdx.x] = 0; cursor[threadIdx.x] = 0; }
}

__global__ void build_offsets(const int* __restrict__ counts, int* __restrict__ seg) {
    if (threadIdx.x == 0) {
        int a = 0;
        for (int e = 0; e < CE; e++) { seg[e] = a; a += counts[e]; }
        seg[CE] = a;
    }
}

__global__ void scatter_tokens(const int* __restrict__ idx, const int* __restrict__ seg,
                               int* __restrict__ cursor, int* __restrict__ perm) {
    int t = blockIdx.x * 256 + threadIdx.x;
    if (t >= CT) return;
    int e = idx[t];
    int p = atomicAdd(&cursor[e], 1);
    perm[seg[e] + p] = t;
}

// ---------------- int8 x ternary GEMM (dp4a) ----------------
// out[m,n] = (sum_k A[m,k]*B[n,k]) * ascale[m] * wscale
// MODE 0: QKV.  z selects weight slice (q/k/v) and dest slice; dest layout [B,NH,S,HD]
// MODE 1: O-proj. out = resid + val, [T,H]
// MODE 2: MoE gate/up. z = expert; rows gathered via perm; out[slot, D]
// MODE 3: MoE down. z = expert; A rows = slots; out scattered: d_out[tok] = resid[tok] + val
template<int MODE>
__global__ void gemm_i8(const int8_t* __restrict__ A, const int8_t* __restrict__ Bw,
                        float* __restrict__ Out,
                        const float* __restrict__ ascale,
                        const float* __restrict__ wscale,
                        const float* __restrict__ resid,
                        const int* __restrict__ perm,
                        const int* __restrict__ seg) {
    int n0 = blockIdx.x * 64;
    int m0 = blockIdx.y * 64;
    int z = blockIdx.z;

    int off = 0, cnt = CT;
    if (MODE >= 2) {
        off = seg[z];
        cnt = seg[z + 1] - off;
        if (m0 >= cnt) return;
    }

    const int8_t* Bz = Bw;
    if (MODE == 0) Bz = Bw + (size_t)z * (CH * CH);
    if (MODE >= 2) Bz = Bw + (size_t)z * ((size_t)CD * CH);

    __shared__ int As[16][64];
    __shared__ int Bs[16][64];

    int tid = threadIdx.x;
    int trow = tid >> 4, tcol = tid & 15;
    int lr = tid >> 2, lk = tid & 3;

    const int8_t* arow;
    {
        int r = m0 + lr;
        if (MODE <= 1) {
            arow = A + (size_t)r * 1024;
        } else if (MODE == 2) {
            int rr = r < cnt - 1 ? r : cnt - 1;
            int tok = perm[off + rr];
            arow = A + (size_t)tok * 1024;
        } else {
            int rr = r < cnt - 1 ? r : cnt - 1;
            arow = A + (size_t)(off + rr) * 1024;
        }
    }
    const int8_t* brow = Bz + (size_t)(n0 + lr) * 1024;

    int acc[4][4];
    #pragma unroll
    for (int i = 0; i < 4; i++)
        #pragma unroll
        for (int j = 0; j < 4; j++) acc[i][j] = 0;

    for (int kt = 0; kt < 1024; kt += 64) {
        int4 av = *(const int4*)(arow + kt + lk * 16);
        int4 bv = *(const int4*)(brow + kt + lk * 16);
        __syncthreads();
        As[lk * 4 + 0][lr] = av.x; As[lk * 4 + 1][lr] = av.y;
        As[lk * 4 + 2][lr] = av.z; As[lk * 4 + 3][lr] = av.w;
        Bs[lk * 4 + 0][lr] = bv.x; Bs[lk * 4 + 1][lr] = bv.y;
        Bs[lk * 4 + 2][lr] = bv.z; Bs[lk * 4 + 3][lr] = bv.w;
        __syncthreads();
        #pragma unroll
        for (int kk = 0; kk < 16; kk++) {
            int4 a4 = *(const int4*)&As[kk][trow * 4];
            int4 b4 = *(const int4*)&Bs[kk][tcol * 4];
            acc[0][0] = __dp4a(a4.x, b4.x, acc[0][0]);
            acc[0][1] = __dp4a(a4.x, b4.y, acc[0][1]);
            acc[0][2] = __dp4a(a4.x, b4.z, acc[0][2]);
            acc[0][3] = __dp4a(a4.x, b4.w, acc[0][3]);
            acc[1][0] = __dp4a(a4.y, b4.x, acc[1][0]);
            acc[1][1] = __dp4a(a4.y, b4.y, acc[1][1]);
            acc[1][2] = __dp4a(a4.y, b4.z, acc[1][2]);
            acc[1][3] = __dp4a(a4.y, b4.w, acc[1][3]);
            acc[2][0] = __dp4a(a4.z, b4.x, acc[2][0]);
            acc[2][1] = __dp4a(a4.z, b4.y, acc[2][1]);
            acc[2][2] = __dp4a(a4.z, b4.z, acc[2][2]);
            acc[2][3] = __dp4a(a4.z, b4.w, acc[2][3]);
            acc[3][0] = __dp4a(a4.w, b4.x, acc[3][0]);
            acc[3][1] = __dp4a(a4.w, b4.y, acc[3][1]);
            acc[3][2] = __dp4a(a4.w, b4.z, acc[3][2]);
            acc[3][3] = __dp4a(a4.w, b4.w, acc[3][3]);
        }
    }

    float wS = wscale[(MODE == 0 || MODE >= 2) ? z : 0];

    #pragma unroll
    for (int i = 0; i < 4; i++) {
        int r = m0 + trow * 4 + i;
        if (MODE == 0) {
            float av = ascale[r] * wS;
            int b = r / CS, sr = r % CS;
            float* dst = Out + (size_t)z * ((size_t)CT * CH);
            #pragma unroll
            for (int j = 0; j < 4; j++) {
                int n = n0 + tcol * 4 + j;
                int nh = n >> 6, d = n & 63;
                dst[(((size_t)b * CNH + nh) * CS + sr) * CHD + d] = acc[i][j] * av;
            }
        } else if (MODE == 1) {
            float av = ascale[r] * wS;
            size_t rb = (size_t)r * CH + n0 + tcol * 4;
            #pragma unroll
            for (int j = 0; j < 4; j++)
                Out[rb + j] = resid[rb + j] + acc[i][j] * av;
        } else if (MODE == 2) {
            if (r < cnt) {
                int tok = perm[off + r];
                float av = ascale[tok] * wS;
                size_t rb = (size_t)(off + r) * CD + n0 + tcol * 4;
                #pragma unroll
                for (int j = 0; j < 4; j++)
                    Out[rb + j] = acc[i][j] * av;
            }
        } else {
            if (r < cnt) {
                int tok = perm[off + r];
                float av = ascale[off + r] * wS;
                size_t rb = (size_t)tok * CH + n0 + tcol * 4;
                #pragma unroll
                for (int j = 0; j < 4; j++)
                    Out[rb + j] = resid[rb + j] + acc[i][j] * av;
            }
        }
    }
}

// ---------------- attention (fp32 flash, 64q x 64k tiles) ----------------
static constexpr int ATTN_SMEM = (64 * 64 * 2 + 64 * 68 * 2 + 3 * 64) * 4;  // 68352 B

__global__ void attn_kernel(const float* __restrict__ Q, const float* __restrict__ Kg,
                            const float* __restrict__ Vg, float* __restrict__ Hout) {
    extern __shared__ float sm[];
    float* Qt = sm;                 // [64 d][64 q]
    float* Kt = Qt + 64 * 64;       // [64 d][64 k]
    float* Vs = Kt + 64 * 64;       // [64 k][68]
    float* Ss = Vs + 64 * 68;       // [64 q][68]
    float* sm_m = Ss + 64 * 68;
    float* sm_l = sm_m + 64;
    float* sm_rs = sm_l + 64;

    int bh = blockIdx.y;
    int q0 = blockIdx.x * 64;
    const float* Qb = Q + (size_t)bh * CS * CHD;
    const float* Kb = Kg + (size_t)bh * CS * CHD;
    const float* Vb = Vg + (size_t)bh * CS * CHD;

    int tid = threadIdx.x;
    int trow = tid >> 4, tcol = tid & 15;
    int lr = tid >> 2, lk = (tid & 3) * 16;

    // load Q tile transposed
    #pragma unroll
    for (int w = 0; w < 4; w++) {
        float4 v = *(const float4*)(Qb + (size_t)(q0 + lr) * CHD + lk + w * 4);
        Qt[(lk + w * 4 + 0) * 64 + lr] = v.x;
        Qt[(lk + w * 4 + 1) * 64 + lr] = v.y;
        Qt[(lk + w * 4 + 2) * 64 + lr] = v.z;
        Qt[(lk + w * 4 + 3) * 64 + lr] = v.w;
    }
    if (tid < 64) { sm_m[tid] = -INFINITY; sm_l[tid] = 0.f; }

    float o[4][4];
    #pragma unroll
    for (int i = 0; i < 4; i++)
        #pragma unroll
        for (int j = 0; j < 4; j++) o[i][j] = 0.f;

    int nkt = blockIdx.x + 1;
    for (int kt = 0; kt < nkt; kt++) {
        int k0 = kt * 64;
        __syncthreads();
        #pragma unroll
        for (int w = 0; w < 4; w++) {
            float4 v = *(const float4*)(Kb + (size_t)(k0 + lr) * CHD + lk + w * 4);
            Kt[(lk + w * 4 + 0) * 64 + lr] = v.x;
            Kt[(lk + w * 4 + 1) * 64 + lr] = v.y;
            Kt[(lk + w * 4 + 2) * 64 + lr] = v.z;
            Kt[(lk + w * 4 + 3) * 64 + lr] = v.w;
            float4 vv = *(const float4*)(Vb + (size_t)(k0 + lr) * CHD + lk + w * 4);
            *(float4*)&Vs[lr * 68 + lk + w * 4] = vv;
        }
        __syncthreads();

        // S = Q.K^T
        float s[4][4];
        #pragma unroll
        for (int i = 0; i < 4; i++)
            #pragma unroll
            for (int j = 0; j < 4; j++) s[i][j] = 0.f;
        #pragma unroll 8
        for (int d = 0; d < 64; d++) {
            float4 a = *(const float4*)&Qt[d * 64 + trow * 4];
            float4 b = *(const float4*)&Kt[d * 64 + tcol * 4];
            s[0][0] += a.x * b.x; s[0][1] += a.x * b.y; s[0][2] += a.x * b.z; s[0][3] += a.x * b.w;
            s[1][0] += a.y * b.x; s[1][1] += a.y * b.y; s[1][2] += a.y * b.z; s[1][3] += a.y * b.w;
            s[2][0] += a.z * b.x; s[2][1] += a.z * b.y; s[2][2] += a.z * b.z; s[2][3] += a.z * b.w;
            s[3][0] += a.w * b.x; s[3][1] += a.w * b.y; s[3][2] += a.w * b.z; s[3][3] += a.w * b.w;
        }
        bool diag = (kt == blockIdx.x);
        #pragma unroll
        for (int i = 0; i < 4; i++) {
            float4 row;
            float* rp = (float*)&row;
            #pragma unroll
            for (int j = 0; j < 4; j++) {
                float sv = s[i][j] * 0.125f;
                if (diag && (k0 + tcol * 4 + j > q0 + trow * 4 + i)) sv = -INFINITY;
                rp[j] = sv;
            }
            *(float4*)&Ss[(trow * 4 + i) * 68 + tcol * 4] = row;
        }
        __syncthreads();

        if (tid < 64) {
            float mo = sm_m[tid];
            float mx = mo;
            float* rr = &Ss[tid * 68];
            #pragma unroll 8
            for (int j = 0; j < 64; j++) mx = fmaxf(mx, rr[j]);
            float rs = expf(mo - mx);   // mo=-inf -> 0
            float sum = 0.f;
            #pragma unroll 8
            for (int j = 0; j < 64; j++) {
                float p = expf(rr[j] - mx);
                rr[j] = p;
                sum += p;
            }
            sm_l[tid] = sm_l[tid] * rs + sum;
            sm_m[tid] = mx;
            sm_rs[tid] = rs;
        }
        __syncthreads();

        // O = O*rs + P.V
        float rs0 = sm_rs[trow * 4 + 0], rs1 = sm_rs[trow * 4 + 1];
        float rs2 = sm_rs[trow * 4 + 2], rs3 = sm_rs[trow * 4 + 3];
        #pragma unroll
        for (int j = 0; j < 4; j++) {
            o[0][j] *= rs0; o[1][j] *= rs1; o[2][j] *= rs2; o[3][j] *= rs3;
        }
        #pragma unroll 4
        for (int kk4 = 0; kk4 < 16; kk4++) {
            float4 p0 = *(const float4*)&Ss[(trow * 4 + 0) * 68 + kk4 * 4];
            float4 p1 = *(const float4*)&Ss[(trow * 4 + 1) * 68 + kk4 * 4];
            float4 p2 = *(const float4*)&Ss[(trow * 4 + 2) * 68 + kk4 * 4];
            float4 p3 = *(const float4*)&Ss[(trow * 4 + 3) * 68 + kk4 * 4];
            const float* pp0 = (const float*)&p0;
            const float* pp1 = (const float*)&p1;
            const float* pp2 = (const float*)&p2;
            const float* pp3 = (const float*)&p3;
            #pragma unroll
            for (int u = 0; u < 4; u++) {
                float4 vv = *(const float4*)&Vs[(kk4 * 4 + u) * 68 + tcol * 4];
                o[0][0] += pp0[u] * vv.x; o[0][1] += pp0[u] * vv.y; o[0][2] += pp0[u] * vv.z; o[0][3] += pp0[u] * vv.w;
                o[1][0] += pp1[u] * vv.x; o[1][1] += pp1[u] * vv.y; o[1][2] += pp1[u] * vv.z; o[1][3] += pp1[u] * vv.w;
                o[2][0] += pp2[u] * vv.x; o[2][1] += pp2[u] * vv.y; o[2][2] += pp2[u] * vv.z; o[2][3] += pp2[u] * vv.w;
                o[3][0] += pp3[u] * vv.x; o[3][1] += pp3[u] * vv.y; o[3][2] += pp3[u] * vv.z; o[3][3] += pp3[u] * vv.w;
            }
        }
    }

    // write [B,S,NH,HD]
    int b = bh / CNH, nh = bh % CNH;
    #pragma unroll
    for (int i = 0; i < 4; i++) {
        int qg = q0 + trow * 4 + i;
        float inv = 1.0f / sm_l[trow * 4 + i];
        #pragma unroll
        for (int j = 0; j < 4; j++)
            Hout[(((size_t)b * CS + qg) * CNH + nh) * CHD + tcol * 4 + j] = o[i][j] * inv;
    }
}

// ---------------- MoE elementwise: hh = relu(g)^2 * u, then act_quant ----------------
__global__ void hh_quant(const float* __restrict__ g, const float* __restrict__ u,
                         int8_t* __restrict__ hq, float* __restrict__ hs) {
    __shared__ float red[256];
    __shared__ float hb[CD];
    int slot = blockIdx.x, tid = threadIdx.x;
    float amax = 0.f;
    #pragma unroll
    for (int i = 0; i < 4; i++) {
        int k = tid + i * 256;
        float gv = g[(size_t)slot * CD + k];
        float uv = u[(size_t)slot * CD + k];
        float rl = fmaxf(gv, 0.f);
        float h = rl * rl * uv;
        hb[k] = h;
        amax = fmaxf(amax, fabsf(h));
    }
    amax = blk_reduce_max(amax, red);
    float m = fmaxf(amax, 1e-5f);
    float s = 127.f / m;
    #pragma unroll
    for (int i = 0; i < 4; i++) {
        int k = tid + i * 256;
        float qv = fminf(fmaxf(rintf(hb[k] * s), -128.f), 127.f);
        hq[(size_t)slot * CD + k] = (int8_t)(int)qv;
    }
    if (tid == 0) hs[slot] = m * (1.0f / 127.f);
}

// ---------------- launch ----------------
extern "C" void kernel_launch(void* const* d_in, const int* in_sizes, int n_in,
                              void* d_out, int out_size) {
    const float* x        = (const float*)d_in[0];
    const float* q_w      = (const float*)d_in[1];
    const float* k_w      = (const float*)d_in[2];
    const float* v_w      = (const float*)d_in[3];
    const float* o_w      = (const float*)d_in[4];
    const float* ln1_w    = (const float*)d_in[5];
    const float* ln2_w    = (const float*)d_in[6];
    const float* router_w = (const float*)d_in[7];
    const float* gate_w   = (const float*)d_in[8];
    const float* up_w     = (const float*)d_in[9];
    const float* down_w   = (const float*)d_in[10];

    unsigned char* base = nullptr;
    cudaGetSymbolAddress((void**)&base, g_scratch);

    int8_t* wq_attn = (int8_t*)(base + OFF_WQ_ATTN);
    int8_t* wq_gate = (int8_t*)(base + OFF_WQ_GATE);
    int8_t* wq_up   = (int8_t*)(base + OFF_WQ_UP);
    int8_t* wq_down = (int8_t*)(base + OFF_WQ_DOWN);
    float*  wsc     = (float*)(base + OFF_WSCALE);
    float*  part    = (float*)(base + OFF_PART);
    int8_t* xq1     = (int8_t*)(base + OFF_XQ1);
    float*  a1s     = (float*)(base + OFF_A1S);
    float*  qkv     = (float*)(base + OFF_QKV);
    float*  hb      = (float*)(base + OFF_HB);
    int8_t* hqa     = (int8_t*)(base + OFF_HQA);
    float*  hsa     = (float*)(base + OFF_HSA);
    float*  x2      = (float*)(base + OFF_X2);
    int8_t* xq2     = (int8_t*)(base + OFF_XQ2);
    float*  a2s     = (float*)(base + OFF_A2S);
    int*    idx     = (int*)(base + OFF_IDX);
    int*    cnt     = (int*)(base + OFF_CNT);
    int*    seg     = (int*)(base + OFF_SEG);
    int*    cur     = (int*)(base + OFF_CUR);
    int*    perm    = (int*)(base + OFF_PERM);
    float*  gb      = (float*)(base + OFF_GB);
    float*  ub      = (float*)(base + OFF_UB);
    int8_t* hqm     = (int8_t*)(base + OFF_HQM);
    float*  hsm     = (float*)(base + OFF_HSM);
    float*  out     = (float*)d_out;

    // ---- weight quantization ----
    absmean_partial<<<dim3(256, 1), 256>>>(q_w, part + 0 * 256, CH * CH);
    absmean_partial<<<dim3(256, 1), 256>>>(k_w, part + 1 * 256, CH * CH);
    absmean_partial<<<dim3(256, 1), 256>>>(v_w, part + 2 * 256, CH * CH);
    absmean_partial<<<dim3(256, 1), 256>>>(o_w, part + 3 * 256, CH * CH);
    absmean_partial<<<dim3(256, 8), 256>>>(gate_w, part + 4 * 256, CD * CH);
    absmean_partial<<<dim3(256, 8), 256>>>(up_w,   part + 12 * 256, CD * CH);
    absmean_partial<<<dim3(256, 8), 256>>>(down_w, part + 20 * 256, CH * CD);
    finalize_wscale<<<1, 32>>>(part, wsc);
    quantize_w<<<dim3(512, 1), 256>>>(q_w, wq_attn + 0 * (CH * CH), wsc, 0, CH * CH);
    quantize_w<<<dim3(512, 1), 256>>>(k_w, wq_attn + 1 * (CH * CH), wsc, 1, CH * CH);
    quantize_w<<<dim3(512, 1), 256>>>(v_w, wq_attn + 2 * (CH * CH), wsc, 2, CH * CH);
    quantize_w<<<dim3(512, 1), 256>>>(o_w, wq_attn + 3 * (CH * CH), wsc, 3, CH * CH);
    quantize_w<<<dim3(512, 8), 256>>>(gate_w, wq_gate, wsc, 4, CD * CH);
    quantize_w<<<dim3(512, 8), 256>>>(up_w,   wq_up,   wsc, 12, CD * CH);
    quantize_w<<<dim3(512, 8), 256>>>(down_w, wq_down, wsc, 20, CH * CD);

    zero_ints<<<1, 32>>>(cnt, cur);

    // ---- attention ----
    rmsnorm_quant<<<CT, 256>>>(x, ln1_w, xq1, a1s);
    gemm_i8<0><<<dim3(16, 64, 3), 256>>>(xq1, wq_attn, qkv, a1s, wsc, nullptr, nullptr, nullptr);

    cudaFuncSetAttribute(attn_kernel, cudaFuncAttributeMaxDynamicSharedMemorySize, ATTN_SMEM);
    attn_kernel<<<dim3(32, CB * CNH), 256, ATTN_SMEM>>>(
        qkv, qkv + (size_t)CT * CH, qkv + 2 * (size_t)CT * CH, hb);

    act_quant_rows<<<CT, 256>>>(hb, hqa, hsa);
    gemm_i8<1><<<dim3(16, 64, 1), 256>>>(hqa, wq_attn + 3 * (CH * CH), x2, hsa, wsc + 3, x, nullptr, nullptr);

    // ---- MoE ----
    rmsnorm2_router<<<CT, 256>>>(x2, ln2_w, router_w, xq2, a2s, idx, cnt);
    build_offsets<<<1, 1>>>(cnt, seg);
    scatter_tokens<<<16, 256>>>(idx, seg, cur, perm);

    gemm_i8<2><<<dim3(16, 64, 8), 256>>>(xq2, wq_gate, gb, a2s, wsc + 4, nullptr, perm, seg);
    gemm_i8<2><<<dim3(16, 64, 8), 256>>>(xq2, wq_up,   ub, a2s, wsc + 12, nullptr, perm, seg);
    hh_quant<<<CT, 256>>>(gb, ub, hqm, hsm);
    gemm_i8<3><<<dim3(16, 64, 8), 256>>>(hqm, wq_down, out, hsm, wsc + 20, x2, perm, seg);
}

// round 3
// speedup vs baseline: 1.2650x; 1.2650x over previous
#include <cuda_runtime.h>
#include <cuda_bf16.h>
#include <mma.h>
#include <math.h>
#include <stdint.h>

using namespace nvcuda;

#define CB 2
#define CS 2048
#define CH 1024
#define CNH 16
#define CHD 64
#define CE 8
#define CD 1024
#define CT (CB*CS)

#define MB (1024ull*1024ull)

// ---------------- scratch layout ----------------
static constexpr size_t OFF_WQ_ATTN = 0;               // 4 MB  int8: q,k,v,o (1MB each)
static constexpr size_t OFF_WQ_GATE = 4*MB;            // 8 MB
static constexpr size_t OFF_WQ_UP   = 12*MB;           // 8 MB
static constexpr size_t OFF_WQ_DOWN = 20*MB;           // 8 MB
static constexpr size_t OFF_WSCALE  = 28*MB;           // 28 floats
static constexpr size_t OFF_PART    = 28*MB + 4096;    // 28*256 floats partial sums
static constexpr size_t OFF_XQ1     = 29*MB;           // 4 MB int8
static constexpr size_t OFF_A1S     = 33*MB;           // T floats
static constexpr size_t OFF_QKV     = 34*MB;           // 24 MB bf16: q,k,v [B,NH,S,HD]
static constexpr size_t OFF_HB      = 82*MB;           // 16 MB fp32 attention out [T,H]
static constexpr size_t OFF_HQA     = 98*MB;           // 4 MB int8
static constexpr size_t OFF_HSA     = 102*MB;          // T floats
static constexpr size_t OFF_X2      = 103*MB;          // 16 MB fp32 (post-attn residual)
static constexpr size_t OFF_XQ2     = 119*MB;          // 4 MB int8
static constexpr size_t OFF_A2S     = 123*MB;          // T floats
static constexpr size_t OFF_IDX     = 123*MB + 64*1024;
static constexpr size_t OFF_CNT     = 123*MB + 128*1024;   // counts[8]
static constexpr size_t OFF_SEG     = 123*MB + 129*1024;   // offsets[9]
static constexpr size_t OFF_CUR     = 123*MB + 130*1024;   // cursor[8]
static constexpr size_t OFF_PERM    = 124*MB;          // T ints
static constexpr size_t OFF_GB      = 125*MB;          // 16 MB fp32
static constexpr size_t OFF_UB      = 141*MB;          // 16 MB fp32
static constexpr size_t OFF_HQM     = 157*MB;          // 4 MB int8
static constexpr size_t OFF_HSM     = 161*MB;          // T floats
static constexpr size_t SCRATCH_BYTES = 162*MB;

__device__ __align__(256) unsigned char g_scratch[SCRATCH_BYTES];

// ---------------- helpers ----------------
__device__ __forceinline__ float blk_reduce_sum(float v, float* red) {
    int tid = threadIdx.x;
    red[tid] = v; __syncthreads();
    #pragma unroll
    for (int s = 128; s > 0; s >>= 1) {
        if (tid < s) red[tid] += red[tid + s];
        __syncthreads();
    }
    float r = red[0]; __syncthreads();
    return r;
}

__device__ __forceinline__ float blk_reduce_max(float v, float* red) {
    int tid = threadIdx.x;
    red[tid] = v; __syncthreads();
    #pragma unroll
    for (int s = 128; s > 0; s >>= 1) {
        if (tid < s) red[tid] = fmaxf(red[tid], red[tid + s]);
        __syncthreads();
    }
    float r = red[0]; __syncthreads();
    return r;
}

// ---------------- weight quantization ----------------
__global__ void absmean_partial(const float* __restrict__ w, float* __restrict__ part, int len) {
    __shared__ float red[256];
    const float* p = w + (size_t)blockIdx.y * len;
    float s = 0.f;
    for (int i = blockIdx.x * 256 + threadIdx.x; i < len; i += gridDim.x * 256)
        s += fabsf(p[i]);
    s = blk_reduce_sum(s, red);
    if (threadIdx.x == 0) part[(size_t)blockIdx.y * gridDim.x + blockIdx.x] = s;
}

// 4 attn matrices in one launch; blockIdx.y selects
__global__ void absmean4(const float* __restrict__ w0, const float* __restrict__ w1,
                         const float* __restrict__ w2, const float* __restrict__ w3,
                         float* __restrict__ part, int len) {
    __shared__ float red[256];
    int sl = blockIdx.y;
    const float* p = sl == 0 ? w0 : sl == 1 ? w1 : sl == 2 ? w2 : w3;
    float s = 0.f;
    for (int i = blockIdx.x * 256 + threadIdx.x; i < len; i += gridDim.x * 256)
        s += fabsf(p[i]);
    s = blk_reduce_sum(s, red);
    if (threadIdx.x == 0) part[(size_t)sl * gridDim.x + blockIdx.x] = s;
}

__global__ void finalize_wscale(const float* __restrict__ part, float* __restrict__ wsc,
                                int i0, int n) {
    int i = i0 + threadIdx.x;
    if (threadIdx.x >= n) return;
    float s = 0.f;
    for (int j = 0; j < 256; j++) s += part[i * 256 + j];
    wsc[i] = fmaxf(s * (1.0f / (1024.f * 1024.f)), 1e-5f);
}

__global__ void quantize_w(const float* __restrict__ w, int8_t* __restrict__ wq,
                           const float* __restrict__ wsc, int widx0, int len) {
    int slice = blockIdx.y;
    float s = 1.0f / wsc[widx0 + slice];
    const float* p = w + (size_t)slice * len;
    int8_t* q = wq + (size_t)slice * len;
    for (int i = blockIdx.x * 256 + threadIdx.x; i < len; i += gridDim.x * 256) {
        float v = rintf(p[i] * s);
        v = fminf(fmaxf(v, -1.f), 1.f);
        q[i] = (int8_t)(int)v;
    }
}

__global__ void quantize4(const float* __restrict__ w0, const float* __restrict__ w1,
                          const float* __restrict__ w2, const float* __restrict__ w3,
                          int8_t* __restrict__ wq, const float* __restrict__ wsc, int len) {
    int sl = blockIdx.y;
    const float* p = sl == 0 ? w0 : sl == 1 ? w1 : sl == 2 ? w2 : w3;
    float s = 1.0f / wsc[sl];
    int8_t* q = wq + (size_t)sl * len;
    for (int i = blockIdx.x * 256 + threadIdx.x; i < len; i += gridDim.x * 256) {
        float v = rintf(p[i] * s);
        v = fminf(fmaxf(v, -1.f), 1.f);
        q[i] = (int8_t)(int)v;
    }
}

// ---------------- activation rmsnorm + quant ----------------
__global__ void rmsnorm_quant(const float* __restrict__ x, const float* __restrict__ lnw,
                              int8_t* __restrict__ xq, float* __restrict__ ainv) {
    __shared__ float red[256];
    __shared__ float xs[CH];
    int t = blockIdx.x, tid = threadIdx.x;
    const float* xr = x + (size_t)t * CH;
    float v[4]; float ss = 0.f;
    #pragma unroll
    for (int i = 0; i < 4; i++) { v[i] = xr[tid + i * 256]; ss += v[i] * v[i]; }
    ss = blk_reduce_sum(ss, red);
    float r = rsqrtf(ss * (1.0f / CH) + 1e-5f);
    float amax = 0.f;
    #pragma unroll
    for (int i = 0; i < 4; i++) {
        float xn = v[i] * r * lnw[tid + i * 256];
        xs[tid + i * 256] = xn;
        amax = fmaxf(amax, fabsf(xn));
    }
    amax = blk_reduce_max(amax, red);
    float m = fmaxf(amax, 1e-5f);
    float s = 127.f / m;
    #pragma unroll
    for (int i = 0; i < 4; i++) {
        float qv = fminf(fmaxf(rintf(xs[tid + i * 256] * s), -128.f), 127.f);
        xq[(size_t)t * CH + tid + i * 256] = (int8_t)(int)qv;
    }
    if (tid == 0) ainv[t] = m * (1.0f / 127.f);
}

__global__ void act_quant_rows(const float* __restrict__ x, int8_t* __restrict__ xq,
                               float* __restrict__ ainv) {
    __shared__ float red[256];
    int t = blockIdx.x, tid = threadIdx.x;
    const float* xr = x + (size_t)t * CH;
    float v[4]; float amax = 0.f;
    #pragma unroll
    for (int i = 0; i < 4; i++) { v[i] = xr[tid + i * 256]; amax = fmaxf(amax, fabsf(v[i])); }
    amax = blk_reduce_max(amax, red);
    float m = fmaxf(amax, 1e-5f);
    float s = 127.f / m;
    #pragma unroll
    for (int i = 0; i < 4; i++) {
        float qv = fminf(fmaxf(rintf(v[i] * s), -128.f), 127.f);
        xq[(size_t)t * CH + tid + i * 256] = (int8_t)(int)qv;
    }
    if (tid == 0) ainv[t] = m * (1.0f / 127.f);
}

__global__ void rmsnorm2_router(const float* __restrict__ x, const float* __restrict__ lnw,
                                const float* __restrict__ rw, int8_t* __restrict__ xq,
                                float* __restrict__ ainv, int* __restrict__ idx,
                                int* __restrict__ counts) {
    __shared__ float red[256];
    __shared__ float xs[CH];
    __shared__ float logits[CE];
    int t = blockIdx.x, tid = threadIdx.x;
    const float* xr = x + (size_t)t * CH;
    float v[4]; float ss = 0.f;
    #pragma unroll
    for (int i = 0; i < 4; i++) { v[i] = xr[tid + i * 256]; ss += v[i] * v[i]; }
    ss = blk_reduce_sum(ss, red);
    float r = rsqrtf(ss * (1.0f / CH) + 1e-5f);
    float amax = 0.f;
    #pragma unroll
    for (int i = 0; i < 4; i++) {
        float xn = v[i] * r * lnw[tid + i * 256];
        xs[tid + i * 256] = xn;
        amax = fmaxf(amax, fabsf(xn));
    }
    amax = blk_reduce_max(amax, red);
    float m = fmaxf(amax, 1e-5f);
    float s = 127.f / m;
    #pragma unroll
    for (int i = 0; i < 4; i++) {
        float qv = fminf(fmaxf(rintf(xs[tid + i * 256] * s), -128.f), 127.f);
        xq[(size_t)t * CH + tid + i * 256] = (int8_t)(int)qv;
    }
    if (tid == 0) ainv[t] = m * (1.0f / 127.f);
    __syncthreads();

    int w = tid >> 5, lane = tid & 31;
    float acc = 0.f;
    for (int h = lane; h < CH; h += 32) acc += xs[h] * rw[w * CH + h];
    #pragma unroll
    for (int o = 16; o > 0; o >>= 1) acc += __shfl_down_sync(0xffffffffu, acc, o);
    if (lane == 0) logits[w] = acc;
    __syncthreads();
    if (tid == 0) {
        float best = logits[0]; int bi = 0;
        #pragma unroll
        for (int e = 1; e < CE; e++) if (logits[e] > best) { best = logits[e]; bi = e; }
        idx[t] = bi;
        atomicAdd(&counts[bi], 1);
    }
}

__global__ void zero_ints(int* __restrict__ counts, int* __restrict__ cursor) {
    if (threadIdx.x < CE) { counts[threadIdx.x] = 0; cursor[threadIdx.x] = 0; }
}

__global__ void build_offsets(const int* __restrict__ counts, int* __restrict__ seg) {
    if (threadIdx.x == 0) {
        int a = 0;
        for (int e = 0; e < CE; e++) { seg[e] = a; a += counts[e]; }
        seg[CE] = a;
    }
}

__global__ void scatter_tokens(const int* __restrict__ idx, const int* __restrict__ seg,
                               int* __restrict__ cursor, int* __restrict__ perm) {
    int t = blockIdx.x * 256 + threadIdx.x;
    if (t >= CT) return;
    int e = idx[t];
    int p = atomicAdd(&cursor[e], 1);
    perm[seg[e] + p] = t;
}

// ---------------- int8 x ternary GEMM (dp4a) ----------------
// MODE 0: QKV -> bf16 dest [3][B,NH,S,HD]
// MODE 1: O-proj. out = resid + val, [T,H] fp32
// MODE 2: MoE gate/up. rows gathered via perm; out[slot, D] fp32
// MODE 3: MoE down. out scattered: out[tok] = resid[tok] + val
template<int MODE>
__global__ void gemm_i8(const int8_t* __restrict__ A, const int8_t* __restrict__ Bw,
                        float* __restrict__ Out, __nv_bfloat16* __restrict__ OutB,
                        const float* __restrict__ ascale,
                        const float* __restrict__ wscale,
                        const float* __restrict__ resid,
                        const int* __restrict__ perm,
                        const int* __restrict__ seg) {
    int n0 = blockIdx.x * 64;
    int m0 = blockIdx.y * 64;
    int z = blockIdx.z;

    int off = 0, cnt = CT;
    if (MODE >= 2) {
        off = seg[z];
        cnt = seg[z + 1] - off;
        if (m0 >= cnt) return;
    }

    const int8_t* Bz = Bw;
    if (MODE == 0) Bz = Bw + (size_t)z * (CH * CH);
    if (MODE >= 2) Bz = Bw + (size_t)z * ((size_t)CD * CH);

    __shared__ int As[16][64];
    __shared__ int Bs[16][64];

    int tid = threadIdx.x;
    int trow = tid >> 4, tcol = tid & 15;
    int lr = tid >> 2, lk = tid & 3;

    const int8_t* arow;
    {
        int r = m0 + lr;
        if (MODE <= 1) {
            arow = A + (size_t)r * 1024;
        } else if (MODE == 2) {
            int rr = r < cnt - 1 ? r : cnt - 1;
            int tok = perm[off + rr];
            arow = A + (size_t)tok * 1024;
        } else {
            int rr = r < cnt - 1 ? r : cnt - 1;
            arow = A + (size_t)(off + rr) * 1024;
        }
    }
    const int8_t* brow = Bz + (size_t)(n0 + lr) * 1024;

    int acc[4][4];
    #pragma unroll
    for (int i = 0; i < 4; i++)
        #pragma unroll
        for (int j = 0; j < 4; j++) acc[i][j] = 0;

    for (int kt = 0; kt < 1024; kt += 64) {
        int4 av = *(const int4*)(arow + kt + lk * 16);
        int4 bv = *(const int4*)(brow + kt + lk * 16);
        __syncthreads();
        As[lk * 4 + 0][lr] = av.x; As[lk * 4 + 1][lr] = av.y;
        As[lk * 4 + 2][lr] = av.z; As[lk * 4 + 3][lr] = av.w;
        Bs[lk * 4 + 0][lr] = bv.x; Bs[lk * 4 + 1][lr] = bv.y;
        Bs[lk * 4 + 2][lr] = bv.z; Bs[lk * 4 + 3][lr] = bv.w;
        __syncthreads();
        #pragma unroll
        for (int kk = 0; kk < 16; kk++) {
            int4 a4 = *(const int4*)&As[kk][trow * 4];
            int4 b4 = *(const int4*)&Bs[kk][tcol * 4];
            acc[0][0] = __dp4a(a4.x, b4.x, acc[0][0]);
            acc[0][1] = __dp4a(a4.x, b4.y, acc[0][1]);
            acc[0][2] = __dp4a(a4.x, b4.z, acc[0][2]);
            acc[0][3] = __dp4a(a4.x, b4.w, acc[0][3]);
            acc[1][0] = __dp4a(a4.y, b4.x, acc[1][0]);
            acc[1][1] = __dp4a(a4.y, b4.y, acc[1][1]);
            acc[1][2] = __dp4a(a4.y, b4.z, acc[1][2]);
            acc[1][3] = __dp4a(a4.y, b4.w, acc[1][3]);
            acc[2][0] = __dp4a(a4.z, b4.x, acc[2][0]);
            acc[2][1] = __dp4a(a4.z, b4.y, acc[2][1]);
            acc[2][2] = __dp4a(a4.z, b4.z, acc[2][2]);
            acc[2][3] = __dp4a(a4.z, b4.w, acc[2][3]);
            acc[3][0] = __dp4a(a4.w, b4.x, acc[3][0]);
            acc[3][1] = __dp4a(a4.w, b4.y, acc[3][1]);
            acc[3][2] = __dp4a(a4.w, b4.z, acc[3][2]);
            acc[3][3] = __dp4a(a4.w, b4.w, acc[3][3]);
        }
    }

    float wS = wscale[(MODE == 0 || MODE >= 2) ? z : 0];

    #pragma unroll
    for (int i = 0; i < 4; i++) {
        int r = m0 + trow * 4 + i;
        if (MODE == 0) {
            float av = ascale[r] * wS;
            int b = r / CS, sr = r % CS;
            __nv_bfloat16* dst = OutB + (size_t)z * ((size_t)CT * CH);
            #pragma unroll
            for (int j = 0; j < 4; j++) {
                int n = n0 + tcol * 4 + j;
                int nh = n >> 6, d = n & 63;
                dst[(((size_t)b * CNH + nh) * CS + sr) * CHD + d] = __float2bfloat16(acc[i][j] * av);
            }
        } else if (MODE == 1) {
            float av = ascale[r] * wS;
            size_t rb = (size_t)r * CH + n0 + tcol * 4;
            #pragma unroll
            for (int j = 0; j < 4; j++)
                Out[rb + j] = resid[rb + j] + acc[i][j] * av;
        } else if (MODE == 2) {
            if (r < cnt) {
                int tok = perm[off + r];
                float av = ascale[tok] * wS;
                size_t rb = (size_t)(off + r) * CD + n0 + tcol * 4;
                #pragma unroll
                for (int j = 0; j < 4; j++)
                    Out[rb + j] = acc[i][j] * av;
            }
        } else {
            if (r < cnt) {
                int tok = perm[off + r];
                float av = ascale[off + r] * wS;
                size_t rb = (size_t)tok * CH + n0 + tcol * 4;
                #pragma unroll
                for (int j = 0; j < 4; j++)
                    Out[rb + j] = resid[rb + j] + acc[i][j] * av;
            }
        }
    }
}

// ---------------- attention: bf16 WMMA flash, 64q x 64k tiles ----------------
// smem: Ss f32[64][72], Os f32[64][72], Qs/Ks/Vs/Ps bf16[64][72], m/l/rs f32[64]
static constexpr int ALD = 72;
static constexpr int ATTN_SMEM = (64*ALD*4)*2 + (64*ALD*2)*4 + 3*64*4;  // 74496

__global__ void __launch_bounds__(128) attn_wmma(
        const __nv_bfloat16* __restrict__ Qg, const __nv_bfloat16* __restrict__ Kg,
        const __nv_bfloat16* __restrict__ Vg, float* __restrict__ Hout) {
    extern __shared__ char smraw[];
    float* Ss = (float*)smraw;                    // 64*72
    float* Os = Ss + 64*ALD;                      // 64*72
    __nv_bfloat16* Qs = (__nv_bfloat16*)(Os + 64*ALD);
    __nv_bfloat16* Ks = Qs + 64*ALD;
    __nv_bfloat16* Vs = Ks + 64*ALD;
    __nv_bfloat16* Ps = Vs + 64*ALD;
    float* m_s  = (float*)(Ps + 64*ALD);
    float* l_s  = m_s + 64;
    float* rs_s = l_s + 64;

    int bh = blockIdx.y;
    int q0 = blockIdx.x * 64;
    const __nv_bfloat16* Qb = Qg + (size_t)bh * CS * CHD;
    const __nv_bfloat16* Kb = Kg + (size_t)bh * CS * CHD;
    const __nv_bfloat16* Vb = Vg + (size_t)bh * CS * CHD;

    int tid = threadIdx.x;
    int w = tid >> 5, lane = tid & 31;

    // load Q tile (64x64 bf16), init O/m/l
    for (int i = tid; i < 512; i += 128) {
        int row = i >> 3, c8 = (i & 7) * 8;
        *(uint4*)&Qs[row * ALD + c8] = *(const uint4*)(Qb + (size_t)(q0 + row) * CHD + c8);
    }
    for (int i = tid; i < 4096; i += 128) Os[(i >> 6) * ALD + (i & 63)] = 0.f;
    if (tid < 64) { m_s[tid] = -INFINITY; l_s[tid] = 0.f; }

    int nkt = blockIdx.x + 1;
    for (int kt = 0; kt < nkt; kt++) {
        int k0 = kt * 64;
        __syncthreads();
        for (int i = tid; i < 512; i += 128) {
            int row = i >> 3, c8 = (i & 7) * 8;
            *(uint4*)&Ks[row * ALD + c8] = *(const uint4*)(Kb + (size_t)(k0 + row) * CHD + c8);
            *(uint4*)&Vs[row * ALD + c8] = *(const uint4*)(Vb + (size_t)(k0 + row) * CHD + c8);
        }
        __syncthreads();

        // S = Q.K^T : warp w computes rows [16w,16w+16) x 64 cols
        {
            wmma::fragment<wmma::accumulator, 16, 16, 16, float> c[4];
            #pragma unroll
            for (int j = 0; j < 4; j++) wmma::fill_fragment(c[j], 0.f);
            #pragma unroll
            for (int kk = 0; kk < 4; kk++) {
                wmma::fragment<wmma::matrix_a, 16, 16, 16, __nv_bfloat16, wmma::row_major> a;
                wmma::load_matrix_sync(a, Qs + (w * 16) * ALD + kk * 16, ALD);
                #pragma unroll
                for (int j = 0; j < 4; j++) {
                    wmma::fragment<wmma::matrix_b, 16, 16, 16, __nv_bfloat16, wmma::col_major> b;
                    wmma::load_matrix_sync(b, Ks + (j * 16) * ALD + kk * 16, ALD);
                    wmma::mma_sync(c[j], a, b, c[j]);
                }
            }
            #pragma unroll
            for (int j = 0; j < 4; j++)
                wmma::store_matrix_sync(Ss + (w * 16) * ALD + j * 16, c[j], ALD, wmma::mem_row_major);
        }
        __syncthreads();

        // online softmax: 2 lanes per row, 32 cols each
        {
            int r = w * 16 + (lane >> 1);
            int c0 = (lane & 1) * 32;
            int qglob = q0 + r;
            int climit = qglob - k0 - c0;   // local col <= climit is valid
            const float* Srow = Ss + r * ALD + c0;
            float mx = -INFINITY;
            #pragma unroll 8
            for (int c = 0; c < 32; c++) {
                float v = Srow[c] * 0.125f;
                if (c <= climit) mx = fmaxf(mx, v);
            }
            mx = fmaxf(mx, __shfl_xor_sync(0xffffffffu, mx, 1));
            float mo = m_s[r];
            float mnew = fmaxf(mo, mx);
            float sum = 0.f;
            #pragma unroll 8
            for (int c = 0; c < 32; c++) {
                float p = 0.f;
                if (c <= climit) p = __expf(Srow[c] * 0.125f - mnew);
                Ps[r * ALD + c0 + c] = __float2bfloat16(p);
                sum += p;
            }
            sum += __shfl_xor_sync(0xffffffffu, sum, 1);
            if ((lane & 1) == 0) {
                float rs = __expf(mo - mnew);
                m_s[r] = mnew;
                l_s[r] = l_s[r] * rs + sum;
                rs_s[r] = rs;
            }
        }
        __syncthreads();

        // rescale O
        for (int i = tid; i < 4096; i += 128) {
            int r = i >> 6, c = i & 63;
            Os[r * ALD + c] *= rs_s[r];
        }
        __syncthreads();

        // O += P.V
        {
            #pragma unroll
            for (int j = 0; j < 4; j++) {
                wmma::fragment<wmma::accumulator, 16, 16, 16, float> c;
                wmma::load_matrix_sync(c, Os + (w * 16) * ALD + j * 16, ALD, wmma::mem_row_major);
                #pragma unroll
                for (int kk = 0; kk < 4; kk++) {
                    wmma::fragment<wmma::matrix_a, 16, 16, 16, __nv_bfloat16, wmma::row_major> a;
                    wmma::fragment<wmma::matrix_b, 16, 16, 16, __nv_bfloat16, wmma::row_major> b;
                    wmma::load_matrix_sync(a, Ps + (w * 16) * ALD + kk * 16, ALD);
                    wmma::load_matrix_sync(b, Vs + (kk * 16) * ALD + j * 16, ALD);
                    wmma::mma_sync(c, a, b, c);
                }
                wmma::store_matrix_sync(Os + (w * 16) * ALD + j * 16, c, ALD, wmma::mem_row_major);
            }
        }
    }
    __syncthreads();

    // write out [B,S,NH,HD]
    int b = bh / CNH, nh = bh % CNH;
    for (int i = tid; i < 4096; i += 128) {
        int r = i >> 6, c = i & 63;
        Hout[(((size_t)b * CS + q0 + r) * CNH + nh) * CHD + c] = Os[r * ALD + c] / l_s[r];
    }
}

// ---------------- MoE elementwise: hh = relu(g)^2 * u, then act_quant ----------------
__global__ void hh_quant(const float* __restrict__ g, const float* __restrict__ u,
                         int8_t* __restrict__ hq, float* __restrict__ hs) {
    __shared__ float red[256];
    __shared__ float hb[CD];
    int slot = blockIdx.x, tid = threadIdx.x;
    float amax = 0.f;
    #pragma unroll
    for (int i = 0; i < 4; i++) {
        int k = tid + i * 256;
        float gv = g[(size_t)slot * CD + k];
        float uv = u[(size_t)slot * CD + k];
        float rl = fmaxf(gv, 0.f);
        float h = rl * rl * uv;
        hb[k] = h;
        amax = fmaxf(amax, fabsf(h));
    }
    amax = blk_reduce_max(amax, red);
    float m = fmaxf(amax, 1e-5f);
    float s = 127.f / m;
    #pragma unroll
    for (int i = 0; i < 4; i++) {
        int k = tid + i * 256;
        float qv = fminf(fmaxf(rintf(hb[k] * s), -128.f), 127.f);
        hq[(size_t)slot * CD + k] = (int8_t)(int)qv;
    }
    if (tid == 0) hs[slot] = m * (1.0f / 127.f);
}

// ---------------- launch ----------------
extern "C" void kernel_launch(void* const* d_in, const int* in_sizes, int n_in,
                              void* d_out, int out_size) {
    const float* x        = (const float*)d_in[0];
    const float* q_w      = (const float*)d_in[1];
    const float* k_w      = (const float*)d_in[2];
    const float* v_w      = (const float*)d_in[3];
    const float* o_w      = (const float*)d_in[4];
    const float* ln1_w    = (const float*)d_in[5];
    const float* ln2_w    = (const float*)d_in[6];
    const float* router_w = (const float*)d_in[7];
    const float* gate_w   = (const float*)d_in[8];
    const float* up_w     = (const float*)d_in[9];
    const float* down_w   = (const float*)d_in[10];

    unsigned char* base = nullptr;
    cudaGetSymbolAddress((void**)&base, g_scratch);

    int8_t* wq_attn = (int8_t*)(base + OFF_WQ_ATTN);
    int8_t* wq_gate = (int8_t*)(base + OFF_WQ_GATE);
    int8_t* wq_up   = (int8_t*)(base + OFF_WQ_UP);
    int8_t* wq_down = (int8_t*)(base + OFF_WQ_DOWN);
    float*  wsc     = (float*)(base + OFF_WSCALE);
    float*  part    = (float*)(base + OFF_PART);
    int8_t* xq1     = (int8_t*)(base + OFF_XQ1);
    float*  a1s     = (float*)(base + OFF_A1S);
    __nv_bfloat16* qkvb = (__nv_bfloat16*)(base + OFF_QKV);
    float*  hb      = (float*)(base + OFF_HB);
    int8_t* hqa     = (int8_t*)(base + OFF_HQA);
    float*  hsa     = (float*)(base + OFF_HSA);
    float*  x2      = (float*)(base + OFF_X2);
    int8_t* xq2     = (int8_t*)(base + OFF_XQ2);
    float*  a2s     = (float*)(base + OFF_A2S);
    int*    idx     = (int*)(base + OFF_IDX);
    int*    cnt     = (int*)(base + OFF_CNT);
    int*    seg     = (int*)(base + OFF_SEG);
    int*    cur     = (int*)(base + OFF_CUR);
    int*    perm    = (int*)(base + OFF_PERM);
    float*  gb      = (float*)(base + OFF_GB);
    float*  ub      = (float*)(base + OFF_UB);
    int8_t* hqm     = (int8_t*)(base + OFF_HQM);
    float*  hsm     = (float*)(base + OFF_HSM);
    float*  out     = (float*)d_out;

    // ---- attention path first (so attn_wmma is the 6th launch for ncu -s 5) ----
    absmean4<<<dim3(256, 4), 256>>>(q_w, k_w, v_w, o_w, part, CH * CH);
    finalize_wscale<<<1, 32>>>(part, wsc, 0, 4);
    quantize4<<<dim3(512, 4), 256>>>(q_w, k_w, v_w, o_w, wq_attn, wsc, CH * CH);
    rmsnorm_quant<<<CT, 256>>>(x, ln1_w, xq1, a1s);
    gemm_i8<0><<<dim3(16, 64, 3), 256>>>(xq1, wq_attn, nullptr, qkvb, a1s, wsc, nullptr, nullptr, nullptr);

    cudaFuncSetAttribute(attn_wmma, cudaFuncAttributeMaxDynamicSharedMemorySize, ATTN_SMEM);
    attn_wmma<<<dim3(32, CB * CNH), 128, ATTN_SMEM>>>(
        qkvb, qkvb + (size_t)CT * CH, qkvb + 2 * (size_t)CT * CH, hb);

    // ---- MoE weight quant (overlaps logically after attention in stream order) ----
    absmean_partial<<<dim3(256, 8), 256>>>(gate_w, part + 4 * 256, CD * CH);
    absmean_partial<<<dim3(256, 8), 256>>>(up_w,   part + 12 * 256, CD * CH);
    absmean_partial<<<dim3(256, 8), 256>>>(down_w, part + 20 * 256, CH * CD);
    finalize_wscale<<<1, 32>>>(part, wsc, 4, 24);
    quantize_w<<<dim3(512, 8), 256>>>(gate_w, wq_gate, wsc, 4, CD * CH);
    quantize_w<<<dim3(512, 8), 256>>>(up_w,   wq_up,   wsc, 12, CD * CH);
    quantize_w<<<dim3(512, 8), 256>>>(down_w, wq_down, wsc, 20, CH * CD);
    zero_ints<<<1, 32>>>(cnt, cur);

    // ---- o-proj + residual ----
    act_quant_rows<<<CT, 256>>>(hb, hqa, hsa);
    gemm_i8<1><<<dim3(16, 64, 1), 256>>>(hqa, wq_attn + 3 * (CH * CH), x2, nullptr, hsa, wsc + 3, x, nullptr, nullptr);

    // ---- MoE ----
    rmsnorm2_router<<<CT, 256>>>(x2, ln2_w, router_w, xq2, a2s, idx, cnt);
    build_offsets<<<1, 1>>>(cnt, seg);
    scatter_tokens<<<16, 256>>>(idx, seg, cur, perm);

    gemm_i8<2><<<dim3(16, 64, 8), 256>>>(xq2, wq_gate, gb, nullptr, a2s, wsc + 4, nullptr, perm, seg);
    gemm_i8<2><<<dim3(16, 64, 8), 256>>>(xq2, wq_up,   ub, nullptr, a2s, wsc + 12, nullptr, perm, seg);
    hh_quant<<<CT, 256>>>(gb, ub, hqm, hsm);
    gemm_i8<3><<<dim3(16, 64, 8), 256>>>(hqm, wq_down, out, nullptr, hsm, wsc + 20, x2, perm, seg);
}